// round 10
// baseline (speedup 1.0000x reference)
#include <cuda_runtime.h>
#include <cstdint>
#include <mma.h>

using namespace nvcuda;

namespace {
constexpr int B  = 4;
constexpr int H  = 16;
constexpr int S  = 1024;
constexpr int D  = 1024;
constexpr int HB = H * B;
constexpr float INV_SCALE = 1.0f / 32.0f;        // 1/sqrt(D)
constexpr size_t OUT_ELEMS = (size_t)B * S * D;

constexpr int QT = 64;                 // q rows per attn block
constexpr int CK = 128;                // k/v chunk rows
constexpr int QS_LD = 68;
constexpr int KV_LD = 68;
constexpr int A3_LD = 132;
constexpr size_t ATTN_SMEM = (size_t)(QT * QS_LD + 2 * CK * KV_LD) * 4;   // 87040
constexpr size_t PROJ_SMEM = (size_t)2 * (128 * 36 + 32 * 132) * 4;       // 70656
constexpr size_t OPROJ_SMEM = (size_t)2 * (128 * 36 + 128 * 36) * 4;      // 73728
}

// Scratch (allocation-free rule: __device__ globals)
__device__ float g_q[(size_t)B * S * H * 64];    // [b*S+s][h*64+k]  (tf32-rounded)
__device__ float g_k[(size_t)B * S * H * 64];
__device__ float g_v[(size_t)B * S * H * 64];
__device__ float g_ctx[(size_t)B * S * H * 64];  // [b*S+q][h*64+v]  (tf32-rounded)
// pre-rounded (tf32) copies of raw inputs
__device__ float g_rq[(size_t)B * S * D];
__device__ float g_rk[(size_t)B * S * D];
__device__ float g_rv[(size_t)B * S * D];
__device__ float g_rwq[(size_t)H * D * 64];
__device__ float g_rwk[(size_t)H * D * 64];
__device__ float g_rwv[(size_t)H * D * 64];
__device__ float g_rwp[(size_t)D * D];

using FragA  = wmma::fragment<wmma::matrix_a, 16, 16, 8, wmma::precision::tf32, wmma::row_major>;
using FragBr = wmma::fragment<wmma::matrix_b, 16, 16, 8, wmma::precision::tf32, wmma::row_major>;
using FragBc = wmma::fragment<wmma::matrix_b, 16, 16, 8, wmma::precision::tf32, wmma::col_major>;
using FragC  = wmma::fragment<wmma::accumulator, 16, 16, 8, float>;

__device__ __forceinline__ void cp_async16(float* dst, const float* src) {
    unsigned int s = (unsigned int)__cvta_generic_to_shared(dst);
    asm volatile("cp.async.cg.shared.global [%0], [%1], 16;" :: "r"(s), "l"(src));
}
__device__ __forceinline__ void cp_commit() { asm volatile("cp.async.commit_group;"); }
template <int N> __device__ __forceinline__ void cp_wait() {
    asm volatile("cp.async.wait_group %0;" :: "n"(N));
}
template <typename F>
__device__ __forceinline__ void to_tf32(F& f) {
#pragma unroll
    for (int i = 0; i < f.num_elements; i++) f.x[i] = wmma::__float_to_tf32(f.x[i]);
}

// ---------------------------------------------------------------------------
// Kernel 0: elementwise tf32 rounding (src -> dst), float4-vectorized.
// ---------------------------------------------------------------------------
__global__ void __launch_bounds__(256)
round_kernel(const float4* __restrict__ src, float4* __restrict__ dst, int n4)
{
    int i = blockIdx.x * 256 + threadIdx.x;
    if (i < n4) {
        float4 v = src[i];
        v.x = wmma::__float_to_tf32(v.x); v.y = wmma::__float_to_tf32(v.y);
        v.z = wmma::__float_to_tf32(v.z); v.w = wmma::__float_to_tf32(v.w);
        dst[i] = v;
    }
}

// ---------------------------------------------------------------------------
// Kernel 1: QKV projections. C[m][h*64+k] = sum_d X[m][d] W[h][d][k]
// Inputs pre-rounded -> no F2FP in the hot loop. Epilogue rounds outputs.
// ---------------------------------------------------------------------------
__global__ void __launch_bounds__(256, 2)
proj_kernel(const float* __restrict__ xq, const float* __restrict__ xk,
            const float* __restrict__ xv, const float* __restrict__ wq,
            const float* __restrict__ wk, const float* __restrict__ wv)
{
    extern __shared__ float sm[];
    float* As = sm;                       // [2][128][36]
    float* Bs = sm + 2 * 128 * 36;        // [2][32][132]

    const int which = blockIdx.z;
    const float* A = (which == 0) ? xq : (which == 1) ? xk : xv;
    const float* W = (which == 0) ? wq : (which == 1) ? wk : wv;
    float* C       = (which == 0) ? g_q : (which == 1) ? g_k : g_v;

    const int m0 = blockIdx.x * 128;
    const int n0 = blockIdx.y * 128;
    const int tid = threadIdx.x;
    const int warp = tid >> 5;
    const int wm = warp & 1, wn = warp >> 1;

    auto prefetch = [&](int kt, int buf) {
        const int k0 = kt * 32;
        float* Ab = As + buf * 128 * 36;
        float* Bb = Bs + buf * 32 * 132;
#pragma unroll
        for (int i = 0; i < 4; i++) {       // 128x32 = 4096 floats
            int lin = tid + i * 256;
            int r = lin >> 3, c = (lin & 7) * 4;
            cp_async16(&Ab[r * 36 + c], A + (size_t)(m0 + r) * D + k0 + c);
        }
#pragma unroll
        for (int i = 0; i < 4; i++) {       // 32x128 = 4096 floats
            int lin = tid + i * 256;
            int r = lin >> 5, c = (lin & 31) * 4;
            int n = n0 + c;
            cp_async16(&Bb[r * 132 + c], W + ((size_t)(n >> 6) * D + k0 + r) * 64 + (n & 63));
        }
        cp_commit();
    };

    FragC acc[4][2];
#pragma unroll
    for (int i = 0; i < 4; i++) { wmma::fill_fragment(acc[i][0], 0.0f); wmma::fill_fragment(acc[i][1], 0.0f); }

    prefetch(0, 0);
    for (int kt = 0; kt < 32; kt++) {
        const int buf = kt & 1;
        if (kt < 31) { prefetch(kt + 1, buf ^ 1); cp_wait<1>(); } else { cp_wait<0>(); }
        __syncthreads();
        float* Ab = As + buf * 128 * 36;
        float* Bb = Bs + buf * 32 * 132;
#pragma unroll
        for (int ks = 0; ks < 4; ks++) {
            FragA a[4]; FragBr bb[2];
#pragma unroll
            for (int i = 0; i < 4; i++) wmma::load_matrix_sync(a[i], &Ab[(wm * 64 + i * 16) * 36 + ks * 8], 36);
#pragma unroll
            for (int j = 0; j < 2; j++) wmma::load_matrix_sync(bb[j], &Bb[(ks * 8) * 132 + wn * 32 + j * 16], 132);
#pragma unroll
            for (int i = 0; i < 4; i++)
#pragma unroll
                for (int j = 0; j < 2; j++) wmma::mma_sync(acc[i][j], a[i], bb[j], acc[i][j]);
        }
        __syncthreads();
    }
#pragma unroll
    for (int i = 0; i < 4; i++)
#pragma unroll
        for (int j = 0; j < 2; j++) {
#pragma unroll
            for (int e = 0; e < acc[i][j].num_elements; e++)
                acc[i][j].x[e] = wmma::__float_to_tf32(acc[i][j].x[e]);
            wmma::store_matrix_sync(C + (size_t)(m0 + wm * 64 + i * 16) * 1024 + n0 + wn * 32 + j * 16,
                                    acc[i][j], 1024, wmma::mem_row_major);
        }
}

// ---------------------------------------------------------------------------
// Kernel 2: fused attention (unchanged from the 852us version).
// ---------------------------------------------------------------------------
__global__ void __launch_bounds__(256, 2)
attn_kernel(float* __restrict__ attn)
{
    extern __shared__ float sm[];
    float* Qs = sm;                    // [64][68]
    float* Kv = sm + QT * QS_LD;       // [2][128][68]  (phase 3 reuses as As3+Vs3)

    const int bh = blockIdx.y;
    const int b = bh / H, h = bh % H;
    const int q0 = blockIdx.x * QT;
    const int tid = threadIdx.x;
    const int warp = tid >> 5, lane = tid & 31;

    float* strip = attn + ((size_t)(h * B + b) * S + q0) * S;   // [64][1024]

    // ---- phase 1: scores = QK^T/32 -> strip ----
    {
#pragma unroll
        for (int i = 0; i < 4; i++) {    // Q tile 64x64 = 4096 floats
            int lin = tid + i * 256;
            int r = lin >> 4, c = (lin & 15) * 4;
            cp_async16(&Qs[r * QS_LD + c], g_q + ((size_t)(b * S + q0 + r)) * 1024 + h * 64 + c);
        }
        auto prefetchK = [&](int c, int buf) {
            float* Kb = Kv + buf * CK * KV_LD;
#pragma unroll
            for (int i = 0; i < 8; i++) {   // K chunk 128x64 = 8192 floats
                int lin = tid + i * 256;
                int r = lin >> 4, cc = (lin & 15) * 4;
                cp_async16(&Kb[r * KV_LD + cc], g_k + ((size_t)(b * S + c * CK + r)) * 1024 + h * 64 + cc);
            }
            cp_commit();
        };
        prefetchK(0, 0);

        const int qh = warp >> 2;        // 0..1 -> 32 rows
        const int kw = warp & 3;         // 0..3 -> 32 cols (within chunk)

        for (int c = 0; c < S / CK; c++) {
            const int buf = c & 1;
            if (c < 7) { prefetchK(c + 1, buf ^ 1); cp_wait<1>(); } else { cp_wait<0>(); }
            __syncthreads();
            float* Kb = Kv + buf * CK * KV_LD;

            FragC acc[2][2];
#pragma unroll
            for (int i = 0; i < 2; i++) { wmma::fill_fragment(acc[i][0], 0.0f); wmma::fill_fragment(acc[i][1], 0.0f); }
#pragma unroll
            for (int ks = 0; ks < 8; ks++) {
                FragA a[2]; FragBc bb[2];
#pragma unroll
                for (int i = 0; i < 2; i++) wmma::load_matrix_sync(a[i], &Qs[(qh * 32 + i * 16) * QS_LD + ks * 8], QS_LD);
#pragma unroll
                for (int j = 0; j < 2; j++) wmma::load_matrix_sync(bb[j], &Kb[(kw * 32 + j * 16) * KV_LD + ks * 8], KV_LD);
#pragma unroll
                for (int i = 0; i < 2; i++)
#pragma unroll
                    for (int j = 0; j < 2; j++) wmma::mma_sync(acc[i][j], a[i], bb[j], acc[i][j]);
            }
#pragma unroll
            for (int i = 0; i < 2; i++)
#pragma unroll
                for (int j = 0; j < 2; j++) {
#pragma unroll
                    for (int e = 0; e < acc[i][j].num_elements; e++) acc[i][j].x[e] *= INV_SCALE;
                    wmma::store_matrix_sync(strip + (size_t)(qh * 32 + i * 16) * S + c * CK + kw * 32 + j * 16,
                                            acc[i][j], S, wmma::mem_row_major);
                }
            __syncthreads();
        }
    }

    // ---- phase 2: softmax in place (rows are L2-hot) ----
#pragma unroll
    for (int rr = 0; rr < 8; rr++) {
        const int row = warp * 8 + rr;
        float* p = strip + (size_t)row * S;
        float4 v[8];
#pragma unroll
        for (int i = 0; i < 8; i++) v[i] = *(float4*)&p[i * 128 + lane * 4];
        float m = -1e30f;
#pragma unroll
        for (int i = 0; i < 8; i++)
            m = fmaxf(m, fmaxf(fmaxf(v[i].x, v[i].y), fmaxf(v[i].z, v[i].w)));
#pragma unroll
        for (int o = 16; o; o >>= 1) m = fmaxf(m, __shfl_xor_sync(0xffffffffu, m, o));
        float s = 0.0f;
#pragma unroll
        for (int i = 0; i < 8; i++) {
            v[i].x = __expf(v[i].x - m); v[i].y = __expf(v[i].y - m);
            v[i].z = __expf(v[i].z - m); v[i].w = __expf(v[i].w - m);
            s += (v[i].x + v[i].y) + (v[i].z + v[i].w);
        }
#pragma unroll
        for (int o = 16; o; o >>= 1) s += __shfl_xor_sync(0xffffffffu, s, o);
        const float inv = 1.0f / s;
#pragma unroll
        for (int i = 0; i < 8; i++) {
            float4 q; q.x = v[i].x * inv; q.y = v[i].y * inv; q.z = v[i].z * inv; q.w = v[i].w * inv;
            *(float4*)&p[i * 128 + lane * 4] = q;
        }
    }
    __syncthreads();

    // ---- phase 3: ctx = P V  (split-k over 2 warp groups) ----
    {
        float* As3 = Kv;                   // [64][132]
        float* Vs3 = Kv + QT * A3_LD;      // [128][68]

        const int kg = warp >> 2;          // 0..1 -> k half of each chunk
        const int qh = (warp >> 1) & 1;    // 0..1 -> 32 rows
        const int vn = warp & 1;           // 0..1 -> 32 cols

        FragC pacc[2][2];
#pragma unroll
        for (int i = 0; i < 2; i++) { wmma::fill_fragment(pacc[i][0], 0.0f); wmma::fill_fragment(pacc[i][1], 0.0f); }

        for (int c = 0; c < S / CK; c++) {
#pragma unroll
            for (int i = 0; i < 8; i++) {          // P chunk 64x128 (L2-hot)
                int lin = tid + i * 256;
                int r = lin >> 5, cc = (lin & 31) * 4;
                cp_async16(&As3[r * A3_LD + cc], strip + (size_t)r * S + c * CK + cc);
            }
#pragma unroll
            for (int i = 0; i < 8; i++) {          // V chunk 128x64
                int lin = tid + i * 256;
                int r = lin >> 4, cc = (lin & 15) * 4;
                cp_async16(&Vs3[r * KV_LD + cc], g_v + ((size_t)(b * S + c * CK + r)) * 1024 + h * 64 + cc);
            }
            cp_commit();
            cp_wait<0>();
            __syncthreads();
#pragma unroll
            for (int ks = 0; ks < 8; ks++) {
                const int kk = kg * 64 + ks * 8;
                FragA a[2]; FragBr bb[2];
#pragma unroll
                for (int i = 0; i < 2; i++) { wmma::load_matrix_sync(a[i], &As3[(qh * 32 + i * 16) * A3_LD + kk], A3_LD); to_tf32(a[i]); }
#pragma unroll
                for (int j = 0; j < 2; j++) wmma::load_matrix_sync(bb[j], &Vs3[kk * KV_LD + vn * 32 + j * 16], KV_LD);
#pragma unroll
                for (int i = 0; i < 2; i++)
#pragma unroll
                    for (int j = 0; j < 2; j++) wmma::mma_sync(pacc[i][j], a[i], bb[j], pacc[i][j]);
            }
            __syncthreads();
        }

        // cross-k reduction via Qs region (64x64, ld 68)
        if (kg == 1) {
#pragma unroll
            for (int i = 0; i < 2; i++)
#pragma unroll
                for (int j = 0; j < 2; j++)
                    wmma::store_matrix_sync(&Qs[(qh * 32 + i * 16) * QS_LD + vn * 32 + j * 16],
                                            pacc[i][j], QS_LD, wmma::mem_row_major);
        }
        __syncthreads();
        if (kg == 0) {
#pragma unroll
            for (int i = 0; i < 2; i++)
#pragma unroll
                for (int j = 0; j < 2; j++) {
                    FragC other;
                    wmma::load_matrix_sync(other, &Qs[(qh * 32 + i * 16) * QS_LD + vn * 32 + j * 16],
                                           QS_LD, wmma::mem_row_major);
#pragma unroll
                    for (int e = 0; e < pacc[i][j].num_elements; e++)
                        pacc[i][j].x[e] = wmma::__float_to_tf32(pacc[i][j].x[e] + other.x[e]);
                    wmma::store_matrix_sync(g_ctx + ((size_t)(b * S + q0 + qh * 32 + i * 16)) * 1024 + h * 64 + vn * 32 + j * 16,
                                            pacc[i][j], 1024, wmma::mem_row_major);
                }
        }
    }
}

// ---------------------------------------------------------------------------
// Kernel 3: out = ctx @ w_proj^T + bias. Weights pre-rounded; bias folded
// into the epilogue via an accumulator-fragment load of a broadcast tile.
// ---------------------------------------------------------------------------
__global__ void __launch_bounds__(256, 2)
outproj_kernel(const float* __restrict__ wproj, const float* __restrict__ bias,
               float* __restrict__ out)
{
    extern __shared__ float sm[];
    float* As = sm;                       // [2][128][36]
    float* Ws = sm + 2 * 128 * 36;        // [2][128][36]

    const int m0 = blockIdx.x * 128;
    const int n0 = blockIdx.y * 128;
    const int tid = threadIdx.x;
    const int warp = tid >> 5;
    const int wm = warp & 1, wn = warp >> 1;

    auto prefetch = [&](int kt, int buf) {
        const int k0 = kt * 32;
        float* Ab = As + buf * 128 * 36;
        float* Wb = Ws + buf * 128 * 36;
#pragma unroll
        for (int i = 0; i < 4; i++) {
            int lin = tid + i * 256;
            int r = lin >> 3, c = (lin & 7) * 4;
            cp_async16(&Ab[r * 36 + c], g_ctx + (size_t)(m0 + r) * 1024 + k0 + c);
            cp_async16(&Wb[r * 36 + c], wproj + (size_t)(n0 + r) * 1024 + k0 + c);
        }
        cp_commit();
    };

    FragC acc[4][2];
#pragma unroll
    for (int i = 0; i < 4; i++) { wmma::fill_fragment(acc[i][0], 0.0f); wmma::fill_fragment(acc[i][1], 0.0f); }

    prefetch(0, 0);
    for (int kt = 0; kt < 32; kt++) {
        const int buf = kt & 1;
        if (kt < 31) { prefetch(kt + 1, buf ^ 1); cp_wait<1>(); } else { cp_wait<0>(); }
        __syncthreads();
        float* Ab = As + buf * 128 * 36;
        float* Wb = Ws + buf * 128 * 36;
#pragma unroll
        for (int ks = 0; ks < 4; ks++) {
            FragA a[4]; FragBc bb[2];
#pragma unroll
            for (int i = 0; i < 4; i++) wmma::load_matrix_sync(a[i], &Ab[(wm * 64 + i * 16) * 36 + ks * 8], 36);
#pragma unroll
            for (int j = 0; j < 2; j++) wmma::load_matrix_sync(bb[j], &Wb[(wn * 32 + j * 16) * 36 + ks * 8], 36);
#pragma unroll
            for (int i = 0; i < 4; i++)
#pragma unroll
                for (int j = 0; j < 2; j++) wmma::mma_sync(acc[i][j], a[i], bb[j], acc[i][j]);
        }
        __syncthreads();
    }

    // ---- bias fold: broadcast bias slice into a 16x128 tile (ld 136), load
    // as accumulator fragments, add elementwise. (Last loop iter ended with a
    // __syncthreads(), so reusing the As region is safe.)
    float* bias_sm = sm;                  // 16 x 136 floats = 8704 B
    {
#pragma unroll
        for (int i = 0; i < 8; i++) {     // 16*128 = 2048 elements
            int lin = tid + i * 256;
            int r = lin >> 7, c = lin & 127;
            bias_sm[r * 136 + c] = bias[n0 + c];
        }
    }
    __syncthreads();

#pragma unroll
    for (int j = 0; j < 2; j++) {
        FragC fb;
        wmma::load_matrix_sync(fb, &bias_sm[wn * 32 + j * 16], 136, wmma::mem_row_major);
#pragma unroll
        for (int i = 0; i < 4; i++) {
#pragma unroll
            for (int e = 0; e < acc[i][j].num_elements; e++) acc[i][j].x[e] += fb.x[e];
            wmma::store_matrix_sync(out + (size_t)(m0 + wm * 64 + i * 16) * D + n0 + wn * 32 + j * 16,
                                    acc[i][j], D, wmma::mem_row_major);
        }
    }
}

// ---------------------------------------------------------------------------

extern "C" void kernel_launch(void* const* d_in, const int* in_sizes, int n_in,
                              void* d_out, int out_size)
{
    const float* query  = (const float*)d_in[0];
    const float* key    = (const float*)d_in[1];
    const float* value  = (const float*)d_in[2];
    const float* w_q    = (const float*)d_in[3];
    const float* w_k    = (const float*)d_in[4];
    const float* w_v    = (const float*)d_in[5];
    const float* w_proj = (const float*)d_in[6];
    const float* b_proj = (const float*)d_in[7];

    float* out  = (float*)d_out;            // [B, S, D]
    float* attn = out + OUT_ELEMS;          // [H*B, S, S]

    cudaFuncSetAttribute(proj_kernel, cudaFuncAttributeMaxDynamicSharedMemorySize, (int)PROJ_SMEM);
    cudaFuncSetAttribute(attn_kernel, cudaFuncAttributeMaxDynamicSharedMemorySize, (int)ATTN_SMEM);
    cudaFuncSetAttribute(outproj_kernel, cudaFuncAttributeMaxDynamicSharedMemorySize, (int)OPROJ_SMEM);

    // resolve device-scratch addresses (host-side; graph-capturable)
    float *rq, *rk, *rv, *rwq, *rwk, *rwv, *rwp;
    cudaGetSymbolAddress((void**)&rq,  g_rq);
    cudaGetSymbolAddress((void**)&rk,  g_rk);
    cudaGetSymbolAddress((void**)&rv,  g_rv);
    cudaGetSymbolAddress((void**)&rwq, g_rwq);
    cudaGetSymbolAddress((void**)&rwk, g_rwk);
    cudaGetSymbolAddress((void**)&rwv, g_rwv);
    cudaGetSymbolAddress((void**)&rwp, g_rwp);

    const int nX4 = (int)((size_t)B * S * D / 4);     // 1,048,576
    const int nW4 = (int)((size_t)H * D * 64 / 4);    // 262,144
    const int nP4 = (int)((size_t)D * D / 4);         // 262,144
    round_kernel<<<(nX4 + 255) / 256, 256>>>((const float4*)query,  (float4*)rq,  nX4);
    round_kernel<<<(nX4 + 255) / 256, 256>>>((const float4*)key,    (float4*)rk,  nX4);
    round_kernel<<<(nX4 + 255) / 256, 256>>>((const float4*)value,  (float4*)rv,  nX4);
    round_kernel<<<(nW4 + 255) / 256, 256>>>((const float4*)w_q,    (float4*)rwq, nW4);
    round_kernel<<<(nW4 + 255) / 256, 256>>>((const float4*)w_k,    (float4*)rwk, nW4);
    round_kernel<<<(nW4 + 255) / 256, 256>>>((const float4*)w_v,    (float4*)rwv, nW4);
    round_kernel<<<(nP4 + 255) / 256, 256>>>((const float4*)w_proj, (float4*)rwp, nP4);

    proj_kernel<<<dim3(32, 8, 3), 256, PROJ_SMEM>>>(rq, rk, rv, rwq, rwk, rwv);
    attn_kernel<<<dim3(S / QT, HB), 256, ATTN_SMEM>>>(attn);
    outproj_kernel<<<dim3(32, 8), 256, OPROJ_SMEM>>>(rwp, b_proj, out);
}

// round 12
// speedup vs baseline: 2.6430x; 2.6430x over previous
#include <cuda_runtime.h>
#include <cstdint>
#include <cuda_fp16.h>
#include <mma.h>

using namespace nvcuda;

namespace {
constexpr int B  = 4;
constexpr int H  = 16;
constexpr int S  = 1024;
constexpr int D  = 1024;
constexpr int HB = H * B;
constexpr float INV_SCALE = 1.0f / 32.0f;        // 1/sqrt(D)
constexpr size_t OUT_ELEMS = (size_t)B * S * D;

// half GEMM tiling
constexpr int G_LD = 72;                         // halfs per smem row (144B)
constexpr int G_BUF = 128 * G_LD;                // halfs per operand buffer
constexpr size_t GEMM_SMEM = (size_t)4 * G_BUF * 2;   // 2 ops x 2 bufs x 2B = 73728

// attention tiling
constexpr int QT = 64;
constexpr int CK = 128;
constexpr int Q_LD = 72;     // halfs
constexpr int K_LD = 72;     // halfs
constexpr int P_LD = 136;    // halfs
constexpr int R_LD = 68;     // floats
constexpr int KV_OFF = QT * Q_LD * 2;            // 9216 bytes, start of Kv region
constexpr size_t ATTN_SMEM = (size_t)KV_OFF + 2 * CK * K_LD * 2;   // 46080
}

// Scratch (__device__ globals; allocation-free rule)
__device__ __half g_hxq[(size_t)B * S * D];
__device__ __half g_hxk[(size_t)B * S * D];
__device__ __half g_hxv[(size_t)B * S * D];
__device__ __half g_hwq[(size_t)D * D];          // transposed [n][d]
__device__ __half g_hwk[(size_t)D * D];
__device__ __half g_hwv[(size_t)D * D];
__device__ __half g_hwp[(size_t)D * D];          // [n][k] (native layout)
__device__ __half g_q[(size_t)B * S * D];        // proj outputs, [m][h*64+k]
__device__ __half g_k[(size_t)B * S * D];
__device__ __half g_v[(size_t)B * S * D];
__device__ __half g_ctx[(size_t)B * S * D];      // [m][h*64+v]
__device__ __half g_hp[(size_t)HB * S * S];      // half copy of attn probs

using HFragA  = wmma::fragment<wmma::matrix_a, 16, 16, 16, __half, wmma::row_major>;
using HFragBr = wmma::fragment<wmma::matrix_b, 16, 16, 16, __half, wmma::row_major>;
using HFragBc = wmma::fragment<wmma::matrix_b, 16, 16, 16, __half, wmma::col_major>;
using HFragC  = wmma::fragment<wmma::accumulator, 16, 16, 16, float>;

__device__ __forceinline__ void cp16h(__half* dst, const __half* src) {
    unsigned int s = (unsigned int)__cvta_generic_to_shared(dst);
    asm volatile("cp.async.cg.shared.global [%0], [%1], 16;" :: "r"(s), "l"(src));
}
__device__ __forceinline__ void cp_commit() { asm volatile("cp.async.commit_group;"); }
template <int N> __device__ __forceinline__ void cp_wait() {
    asm volatile("cp.async.wait_group %0;" :: "n"(N));
}

// ---------------------------------------------------------------------------
// Kernel 0a: fp32 -> fp16 conversion (RN), float4 in / 4 halfs out.
// ---------------------------------------------------------------------------
__global__ void __launch_bounds__(256)
f2h_kernel(const float4* __restrict__ src, __half2* __restrict__ dst, int n4)
{
    int i = blockIdx.x * 256 + threadIdx.x;
    if (i < n4) {
        float4 v = src[i];
        dst[2 * i + 0] = __floats2half2_rn(v.x, v.y);
        dst[2 * i + 1] = __floats2half2_rn(v.z, v.w);
    }
}

// ---------------------------------------------------------------------------
// Kernel 0b: W[h][d][kk] -> Wt[(h*64+kk)][d] in fp16.
// grid (D/64, H, 3), block 256.
// ---------------------------------------------------------------------------
__global__ void __launch_bounds__(256)
wtrans_kernel(const float* __restrict__ wq, const float* __restrict__ wk,
              const float* __restrict__ wv)
{
    const int which = blockIdx.z;
    const float* W = (which == 0) ? wq : (which == 1) ? wk : wv;
    __half* OUT    = (which == 0) ? g_hwq : (which == 1) ? g_hwk : g_hwv;

    const int h  = blockIdx.y;
    const int d0 = blockIdx.x * 64;
    const int tid = threadIdx.x;
    __shared__ float t[64][65];

#pragma unroll
    for (int i = 0; i < 4; i++) {
        int idx = tid + i * 256;
        int r = idx >> 4, c4 = idx & 15;
        float4 v = *(const float4*)(W + ((size_t)h * 1024 + d0 + r) * 64 + c4 * 4);
        t[r][c4 * 4 + 0] = v.x; t[r][c4 * 4 + 1] = v.y;
        t[r][c4 * 4 + 2] = v.z; t[r][c4 * 4 + 3] = v.w;
    }
    __syncthreads();
#pragma unroll
    for (int i = 0; i < 4; i++) {
        int idx = tid + i * 256;
        int kk = idx >> 4, c4 = idx & 15;
        __half2* d = (__half2*)(OUT + ((size_t)h * 64 + kk) * 1024 + d0 + c4 * 4);
        d[0] = __floats2half2_rn(t[c4 * 4 + 0][kk], t[c4 * 4 + 1][kk]);
        d[1] = __floats2half2_rn(t[c4 * 4 + 2][kk], t[c4 * 4 + 3][kk]);
    }
}

// ---------------------------------------------------------------------------
// Kernel 1: fp16 GEMM, C[m][n] = sum_k A[m][k] * Bm[n][k].  M=4096, N=K=1024.
// 128x128 CTA tile, 8 warps (warp tile 64x32), K slabs of 64, double buffer.
// out_half=1 -> C is __half; else C is float with optional bias.
// ---------------------------------------------------------------------------
__global__ void __launch_bounds__(256, 2)
hgemm_kernel(const __half* __restrict__ A, const __half* __restrict__ Bm,
             void* __restrict__ Cout, const float* __restrict__ bias, int out_half)
{
    extern __shared__ char smc[];
    __half* As = (__half*)smc;            // [2][128][G_LD]
    __half* Bs = As + 2 * G_BUF;          // [2][128][G_LD]

    const int tid = threadIdx.x;
    const int w = tid >> 5, lane = tid & 31;
    const int wm = w & 1, wn = w >> 1;
    const int m0 = blockIdx.x * 128;
    const int n0 = blockIdx.y * 128;

    auto prefetch = [&](int s, int buf) {
        const int k0 = s * 64;
        __half* Ab = As + buf * G_BUF;
        __half* Bb = Bs + buf * G_BUF;
#pragma unroll
        for (int i = 0; i < 4; i++) {          // 128 rows x 64 halfs each operand
            int idx = tid + i * 256;
            int r = idx >> 3, c = idx & 7;     // c*8 halfs = 16B
            cp16h(&Ab[r * G_LD + c * 8], A + (size_t)(m0 + r) * 1024 + k0 + c * 8);
            cp16h(&Bb[r * G_LD + c * 8], Bm + (size_t)(n0 + r) * 1024 + k0 + c * 8);
        }
        cp_commit();
    };

    HFragC acc[4][2];
#pragma unroll
    for (int i = 0; i < 4; i++) { wmma::fill_fragment(acc[i][0], 0.0f); wmma::fill_fragment(acc[i][1], 0.0f); }

    prefetch(0, 0);
    for (int s = 0; s < 16; s++) {
        const int buf = s & 1;
        if (s < 15) { prefetch(s + 1, buf ^ 1); cp_wait<1>(); } else { cp_wait<0>(); }
        __syncthreads();
        __half* Ab = As + buf * G_BUF;
        __half* Bb = Bs + buf * G_BUF;
#pragma unroll
        for (int ks = 0; ks < 4; ks++) {
            HFragA a[4]; HFragBc bb[2];
#pragma unroll
            for (int i = 0; i < 4; i++)
                wmma::load_matrix_sync(a[i], &Ab[(wm * 64 + i * 16) * G_LD + ks * 16], G_LD);
#pragma unroll
            for (int j = 0; j < 2; j++)
                wmma::load_matrix_sync(bb[j], &Bb[(wn * 32 + j * 16) * G_LD + ks * 16], G_LD);
#pragma unroll
            for (int i = 0; i < 4; i++)
#pragma unroll
                for (int j = 0; j < 2; j++) wmma::mma_sync(acc[i][j], a[i], bb[j], acc[i][j]);
        }
        __syncthreads();
    }

    // ---- epilogue: per-warp smem patch (16x36 f32), coalesced writes ----
    float* stg = (float*)smc + w * 576;       // 16*36 floats per warp
    const int r = lane >> 1, cq = (lane & 1) * 16;
    float4 bv[4];
    if (!out_half) {
#pragma unroll
        for (int q = 0; q < 4; q++)
            bv[q] = bias ? *(const float4*)&bias[n0 + wn * 32 + cq + q * 4]
                         : make_float4(0.f, 0.f, 0.f, 0.f);
    }
#pragma unroll
    for (int i = 0; i < 4; i++) {
        wmma::store_matrix_sync(stg,      acc[i][0], 36, wmma::mem_row_major);
        wmma::store_matrix_sync(stg + 16, acc[i][1], 36, wmma::mem_row_major);
        __syncwarp();
        float4 v[4];
#pragma unroll
        for (int q = 0; q < 4; q++) v[q] = *(float4*)&stg[r * 36 + cq + q * 4];
        size_t gr = (size_t)(m0 + wm * 64 + i * 16 + r) * 1024 + n0 + wn * 32 + cq;
        if (out_half) {
            __half hb[16];
#pragma unroll
            for (int q = 0; q < 4; q++) {
                ((__half2*)hb)[2 * q + 0] = __floats2half2_rn(v[q].x, v[q].y);
                ((__half2*)hb)[2 * q + 1] = __floats2half2_rn(v[q].z, v[q].w);
            }
            __half* hC = (__half*)Cout;
            *(uint4*)&hC[gr]     = ((uint4*)hb)[0];
            *(uint4*)&hC[gr + 8] = ((uint4*)hb)[1];
        } else {
            float* fC = (float*)Cout;
#pragma unroll
            for (int q = 0; q < 4; q++) {
                v[q].x += bv[q].x; v[q].y += bv[q].y; v[q].z += bv[q].z; v[q].w += bv[q].w;
                *(float4*)&fC[gr + q * 4] = v[q];
            }
        }
        __syncwarp();
    }
}

// ---------------------------------------------------------------------------
// Kernel 2: fused attention (fp16 operands, fp32 scores/softmax).
// grid (S/64, HB), block 256, smem 46080.
// ---------------------------------------------------------------------------
__global__ void __launch_bounds__(256, 2)
attn_kernel(float* __restrict__ attn)
{
    extern __shared__ char smc[];
    __half* Qs = (__half*)smc;                     // [64][Q_LD]
    __half* Kv = (__half*)(smc + KV_OFF);          // [2][128][K_LD]
    __half* As3 = (__half*)(smc + KV_OFF);         // [64][P_LD]
    __half* Vs3 = (__half*)(smc + KV_OFF + QT * P_LD * 2);   // [128][K_LD]
    float* red  = (float*)(smc + KV_OFF);                    // [64][R_LD]
    float* red2 = (float*)(smc + KV_OFF + QT * P_LD * 2);    // [64][R_LD]

    const int bh = blockIdx.y;
    const int b = bh / H, h = bh % H;
    const int q0 = blockIdx.x * QT;
    const int tid = threadIdx.x;
    const int warp = tid >> 5, lane = tid & 31;

    float*  strip  = attn + ((size_t)(h * B + b) * S + q0) * S;    // [64][1024] f32
    __half* hstrip = g_hp + ((size_t)(h * B + b) * S + q0) * S;    // [64][1024] f16

    // ---- phase 1: scores = QK^T/32 -> strip (f32) ----
    {
#pragma unroll
        for (int i = 0; i < 2; i++) {    // Q tile 64x64 halfs = 512 x 16B
            int idx = tid + i * 256;
            int r = idx >> 3, c = idx & 7;
            cp16h(&Qs[r * Q_LD + c * 8], g_q + ((size_t)(b * S + q0 + r)) * 1024 + h * 64 + c * 8);
        }
        auto prefetchK = [&](int c, int buf) {
            __half* Kb = Kv + buf * CK * K_LD;
#pragma unroll
            for (int i = 0; i < 4; i++) {   // K chunk 128x64 halfs = 1024 x 16B
                int idx = tid + i * 256;
                int r = idx >> 3, cc = idx & 7;
                cp16h(&Kb[r * K_LD + cc * 8],
                      g_k + ((size_t)(b * S + c * CK + r)) * 1024 + h * 64 + cc * 8);
            }
            cp_commit();
        };
        prefetchK(0, 0);

        const int qh = warp >> 2;        // 0..1 -> 32 q rows
        const int kw = warp & 3;         // 0..3 -> 32 keys

        for (int c = 0; c < S / CK; c++) {
            const int buf = c & 1;
            if (c < 7) { prefetchK(c + 1, buf ^ 1); cp_wait<1>(); } else { cp_wait<0>(); }
            __syncthreads();
            __half* Kb = Kv + buf * CK * K_LD;

            HFragC acc[2][2];
#pragma unroll
            for (int i = 0; i < 2; i++) { wmma::fill_fragment(acc[i][0], 0.0f); wmma::fill_fragment(acc[i][1], 0.0f); }
#pragma unroll
            for (int ks = 0; ks < 4; ks++) {
                HFragA a[2]; HFragBc bb[2];
#pragma unroll
                for (int i = 0; i < 2; i++)
                    wmma::load_matrix_sync(a[i], &Qs[(qh * 32 + i * 16) * Q_LD + ks * 16], Q_LD);
#pragma unroll
                for (int j = 0; j < 2; j++)
                    wmma::load_matrix_sync(bb[j], &Kb[(kw * 32 + j * 16) * K_LD + ks * 16], K_LD);
#pragma unroll
                for (int i = 0; i < 2; i++)
#pragma unroll
                    for (int j = 0; j < 2; j++) wmma::mma_sync(acc[i][j], a[i], bb[j], acc[i][j]);
            }
#pragma unroll
            for (int i = 0; i < 2; i++)
#pragma unroll
                for (int j = 0; j < 2; j++) {
#pragma unroll
                    for (int e = 0; e < acc[i][j].num_elements; e++) acc[i][j].x[e] *= INV_SCALE;
                    wmma::store_matrix_sync(strip + (size_t)(qh * 32 + i * 16) * S + c * CK + kw * 32 + j * 16,
                                            acc[i][j], S, wmma::mem_row_major);
                }
            __syncthreads();
        }
    }

    // ---- phase 2: softmax in place (f32) + half P copy ----
#pragma unroll
    for (int rr = 0; rr < 8; rr++) {
        const int row = warp * 8 + rr;
        float* p = strip + (size_t)row * S;
        __half* hp = hstrip + (size_t)row * S;
        float4 v[8];
#pragma unroll
        for (int i = 0; i < 8; i++) v[i] = *(float4*)&p[i * 128 + lane * 4];
        float m = -1e30f;
#pragma unroll
        for (int i = 0; i < 8; i++)
            m = fmaxf(m, fmaxf(fmaxf(v[i].x, v[i].y), fmaxf(v[i].z, v[i].w)));
#pragma unroll
        for (int o = 16; o; o >>= 1) m = fmaxf(m, __shfl_xor_sync(0xffffffffu, m, o));
        float s = 0.0f;
#pragma unroll
        for (int i = 0; i < 8; i++) {
            v[i].x = __expf(v[i].x - m); v[i].y = __expf(v[i].y - m);
            v[i].z = __expf(v[i].z - m); v[i].w = __expf(v[i].w - m);
            s += (v[i].x + v[i].y) + (v[i].z + v[i].w);
        }
#pragma unroll
        for (int o = 16; o; o >>= 1) s += __shfl_xor_sync(0xffffffffu, s, o);
        const float inv = 1.0f / s;
#pragma unroll
        for (int i = 0; i < 8; i++) {
            float4 q; q.x = v[i].x * inv; q.y = v[i].y * inv; q.z = v[i].z * inv; q.w = v[i].w * inv;
            *(float4*)&p[i * 128 + lane * 4] = q;
            __half2* hp2 = (__half2*)&hp[i * 128 + lane * 4];
            hp2[0] = __floats2half2_rn(q.x, q.y);
            hp2[1] = __floats2half2_rn(q.z, q.w);
        }
    }
    __syncthreads();

    // ---- phase 3: ctx = P V  (split-k over 2 warp groups, fp16 operands) ----
    {
        const int kg = warp >> 2;
        const int qh = (warp >> 1) & 1;
        const int vn = warp & 1;

        HFragC pacc[2][2];
#pragma unroll
        for (int i = 0; i < 2; i++) { wmma::fill_fragment(pacc[i][0], 0.0f); wmma::fill_fragment(pacc[i][1], 0.0f); }

        for (int c = 0; c < S / CK; c++) {
#pragma unroll
            for (int i = 0; i < 4; i++) {          // P chunk 64x128 halfs = 1024 x 16B
                int idx = tid + i * 256;
                int r = idx >> 4, cc = idx & 15;
                cp16h(&As3[r * P_LD + cc * 8], hstrip + (size_t)r * S + c * CK + cc * 8);
            }
#pragma unroll
            for (int i = 0; i < 4; i++) {          // V chunk 128x64 halfs = 1024 x 16B
                int idx = tid + i * 256;
                int r = idx >> 3, cc = idx & 7;
                cp16h(&Vs3[r * K_LD + cc * 8],
                      g_v + ((size_t)(b * S + c * CK + r)) * 1024 + h * 64 + cc * 8);
            }
            cp_commit();
            cp_wait<0>();
            __syncthreads();
#pragma unroll
            for (int ks = 0; ks < 4; ks++) {
                const int kk = kg * 64 + ks * 16;
                HFragA a[2]; HFragBr bb[2];
#pragma unroll
                for (int i = 0; i < 2; i++)
                    wmma::load_matrix_sync(a[i], &As3[(qh * 32 + i * 16) * P_LD + kk], P_LD);
#pragma unroll
                for (int j = 0; j < 2; j++)
                    wmma::load_matrix_sync(bb[j], &Vs3[kk * K_LD + vn * 32 + j * 16], K_LD);
#pragma unroll
                for (int i = 0; i < 2; i++)
#pragma unroll
                    for (int j = 0; j < 2; j++) wmma::mma_sync(pacc[i][j], a[i], bb[j], pacc[i][j]);
            }
            __syncthreads();
        }

        // cross-kg reduction in f32 smem, then half write of ctx
        if (kg == 1) {
#pragma unroll
            for (int i = 0; i < 2; i++)
#pragma unroll
                for (int j = 0; j < 2; j++)
                    wmma::store_matrix_sync(&red[(qh * 32 + i * 16) * R_LD + vn * 32 + j * 16],
                                            pacc[i][j], R_LD, wmma::mem_row_major);
        }
        __syncthreads();
        if (kg == 0) {
#pragma unroll
            for (int i = 0; i < 2; i++)
#pragma unroll
                for (int j = 0; j < 2; j++) {
                    HFragC other;
                    wmma::load_matrix_sync(other, &red[(qh * 32 + i * 16) * R_LD + vn * 32 + j * 16],
                                           R_LD, wmma::mem_row_major);
#pragma unroll
                    for (int e = 0; e < pacc[i][j].num_elements; e++) pacc[i][j].x[e] += other.x[e];
                    wmma::store_matrix_sync(&red2[(qh * 32 + i * 16) * R_LD + vn * 32 + j * 16],
                                            pacc[i][j], R_LD, wmma::mem_row_major);
                }
        }
        __syncthreads();
        // copy red2 (64x64 f32) -> g_ctx as half
#pragma unroll
        for (int i = 0; i < 8; i++) {
            int lin = tid + i * 256;            // 2048 float2 pairs
            int r = lin >> 5, c2 = lin & 31;
            float2 t = *(float2*)&red2[r * R_LD + c2 * 2];
            __half2* dst = (__half2*)(g_ctx + ((size_t)(b * S + q0 + r)) * 1024 + h * 64 + c2 * 2);
            *dst = __floats2half2_rn(t.x, t.y);
        }
    }
}

// ---------------------------------------------------------------------------

extern "C" void kernel_launch(void* const* d_in, const int* in_sizes, int n_in,
                              void* d_out, int out_size)
{
    const float* query  = (const float*)d_in[0];
    const float* key    = (const float*)d_in[1];
    const float* value  = (const float*)d_in[2];
    const float* w_q    = (const float*)d_in[3];
    const float* w_k    = (const float*)d_in[4];
    const float* w_v    = (const float*)d_in[5];
    const float* w_proj = (const float*)d_in[6];
    const float* b_proj = (const float*)d_in[7];

    float* out  = (float*)d_out;            // [B, S, D]
    float* attn = out + OUT_ELEMS;          // [H*B, S, S]

    cudaFuncSetAttribute(hgemm_kernel, cudaFuncAttributeMaxDynamicSharedMemorySize, (int)GEMM_SMEM);
    cudaFuncSetAttribute(attn_kernel, cudaFuncAttributeMaxDynamicSharedMemorySize, (int)ATTN_SMEM);

    __half *hxq, *hxk, *hxv, *hwq, *hwk, *hwv, *hwp, *q, *k, *v, *ctx;
    cudaGetSymbolAddress((void**)&hxq, g_hxq);
    cudaGetSymbolAddress((void**)&hxk, g_hxk);
    cudaGetSymbolAddress((void**)&hxv, g_hxv);
    cudaGetSymbolAddress((void**)&hwq, g_hwq);
    cudaGetSymbolAddress((void**)&hwk, g_hwk);
    cudaGetSymbolAddress((void**)&hwv, g_hwv);
    cudaGetSymbolAddress((void**)&hwp, g_hwp);
    cudaGetSymbolAddress((void**)&q,   g_q);
    cudaGetSymbolAddress((void**)&k,   g_k);
    cudaGetSymbolAddress((void**)&v,   g_v);
    cudaGetSymbolAddress((void**)&ctx, g_ctx);

    const int nX4 = (int)((size_t)B * S * D / 4);   // 1,048,576
    const int nP4 = (int)((size_t)D * D / 4);       // 262,144
    f2h_kernel<<<(nX4 + 255) / 256, 256>>>((const float4*)query,  (__half2*)hxq, nX4);
    f2h_kernel<<<(nX4 + 255) / 256, 256>>>((const float4*)key,    (__half2*)hxk, nX4);
    f2h_kernel<<<(nX4 + 255) / 256, 256>>>((const float4*)value,  (__half2*)hxv, nX4);
    f2h_kernel<<<(nP4 + 255) / 256, 256>>>((const float4*)w_proj, (__half2*)hwp, nP4);
    wtrans_kernel<<<dim3(16, 16, 3), 256>>>(w_q, w_k, w_v);

    hgemm_kernel<<<dim3(32, 8), 256, GEMM_SMEM>>>(hxq, hwq, q,   nullptr, 1);
    hgemm_kernel<<<dim3(32, 8), 256, GEMM_SMEM>>>(hxk, hwk, k,   nullptr, 1);
    hgemm_kernel<<<dim3(32, 8), 256, GEMM_SMEM>>>(hxv, hwv, v,   nullptr, 1);

    attn_kernel<<<dim3(S / QT, HB), 256, ATTN_SMEM>>>(attn);

    hgemm_kernel<<<dim3(32, 8), 256, GEMM_SMEM>>>(ctx, hwp, out, b_proj, 0);
}

// round 13
// speedup vs baseline: 2.7811x; 1.0523x over previous
#include <cuda_runtime.h>
#include <cstdint>
#include <cuda_fp16.h>
#include <mma.h>

using namespace nvcuda;

namespace {
constexpr int B  = 4;
constexpr int H  = 16;
constexpr int S  = 1024;
constexpr int D  = 1024;
constexpr int HB = H * B;
constexpr float INV_SCALE = 1.0f / 32.0f;        // 1/sqrt(D)
constexpr size_t OUT_ELEMS = (size_t)B * S * D;

// half GEMM tiling
constexpr int G_LD = 72;                         // halfs per smem row (144B)
constexpr int G_BUF = 128 * G_LD;                // halfs per operand buffer
constexpr size_t GEMM_SMEM = (size_t)4 * G_BUF * 2;   // 73728

// attention tiling
constexpr int QT = 64;
constexpr int CK = 128;
constexpr int Q_LD = 72;     // halfs
constexpr int K_LD = 72;     // halfs
constexpr int P_LD = 136;    // halfs
constexpr int R_LD = 68;     // floats
constexpr int KV_OFF = QT * Q_LD * 2;            // 9216 bytes
constexpr size_t ATTN_SMEM = (size_t)KV_OFF + 2 * CK * K_LD * 2;   // 46080
}

// Scratch (__device__ globals; allocation-free rule)
__device__ __half g_hxq[(size_t)B * S * D];
__device__ __half g_hxk[(size_t)B * S * D];
__device__ __half g_hxv[(size_t)B * S * D];
__device__ __half g_hwq[(size_t)D * D];          // transposed [n][d]
__device__ __half g_hwk[(size_t)D * D];
__device__ __half g_hwv[(size_t)D * D];
__device__ __half g_hwp[(size_t)D * D];          // [n][k]
__device__ __half g_q[(size_t)B * S * D];        // proj outputs, [m][h*64+k]
__device__ __half g_k[(size_t)B * S * D];
__device__ __half g_v[(size_t)B * S * D];
__device__ __half g_ctx[(size_t)B * S * D];      // [m][h*64+v]

using HFragA  = wmma::fragment<wmma::matrix_a, 16, 16, 16, __half, wmma::row_major>;
using HFragBr = wmma::fragment<wmma::matrix_b, 16, 16, 16, __half, wmma::row_major>;
using HFragBc = wmma::fragment<wmma::matrix_b, 16, 16, 16, __half, wmma::col_major>;
using HFragC  = wmma::fragment<wmma::accumulator, 16, 16, 16, float>;

__device__ __forceinline__ void cp16h(__half* dst, const __half* src) {
    unsigned int s = (unsigned int)__cvta_generic_to_shared(dst);
    asm volatile("cp.async.cg.shared.global [%0], [%1], 16;" :: "r"(s), "l"(src));
}
__device__ __forceinline__ void cp_commit() { asm volatile("cp.async.commit_group;"); }
template <int N> __device__ __forceinline__ void cp_wait() {
    asm volatile("cp.async.wait_group %0;" :: "n"(N));
}

// ---------------------------------------------------------------------------
// Kernel 0a: fp32 -> fp16 for the three X tensors in one launch (z-indexed).
// ---------------------------------------------------------------------------
__global__ void __launch_bounds__(256)
f2h3_kernel(const float4* __restrict__ s0, const float4* __restrict__ s1,
            const float4* __restrict__ s2, int n4)
{
    const float4* src = (blockIdx.y == 0) ? s0 : (blockIdx.y == 1) ? s1 : s2;
    __half2* dst = (blockIdx.y == 0) ? (__half2*)g_hxq
                 : (blockIdx.y == 1) ? (__half2*)g_hxk : (__half2*)g_hxv;
    int i = blockIdx.x * 256 + threadIdx.x;
    if (i < n4) {
        float4 v = src[i];
        dst[2 * i + 0] = __floats2half2_rn(v.x, v.y);
        dst[2 * i + 1] = __floats2half2_rn(v.z, v.w);
    }
}

__global__ void __launch_bounds__(256)
f2h_kernel(const float4* __restrict__ src, __half2* __restrict__ dst, int n4)
{
    int i = blockIdx.x * 256 + threadIdx.x;
    if (i < n4) {
        float4 v = src[i];
        dst[2 * i + 0] = __floats2half2_rn(v.x, v.y);
        dst[2 * i + 1] = __floats2half2_rn(v.z, v.w);
    }
}

// ---------------------------------------------------------------------------
// Kernel 0b: W[h][d][kk] -> Wt[(h*64+kk)][d] in fp16. grid (16, 16, 3).
// ---------------------------------------------------------------------------
__global__ void __launch_bounds__(256)
wtrans_kernel(const float* __restrict__ wq, const float* __restrict__ wk,
              const float* __restrict__ wv)
{
    const int which = blockIdx.z;
    const float* W = (which == 0) ? wq : (which == 1) ? wk : wv;
    __half* OUT    = (which == 0) ? g_hwq : (which == 1) ? g_hwk : g_hwv;

    const int h  = blockIdx.y;
    const int d0 = blockIdx.x * 64;
    const int tid = threadIdx.x;
    __shared__ float t[64][65];

#pragma unroll
    for (int i = 0; i < 4; i++) {
        int idx = tid + i * 256;
        int r = idx >> 4, c4 = idx & 15;
        float4 v = *(const float4*)(W + ((size_t)h * 1024 + d0 + r) * 64 + c4 * 4);
        t[r][c4 * 4 + 0] = v.x; t[r][c4 * 4 + 1] = v.y;
        t[r][c4 * 4 + 2] = v.z; t[r][c4 * 4 + 3] = v.w;
    }
    __syncthreads();
#pragma unroll
    for (int i = 0; i < 4; i++) {
        int idx = tid + i * 256;
        int kk = idx >> 4, c4 = idx & 15;
        __half2* d = (__half2*)(OUT + ((size_t)h * 64 + kk) * 1024 + d0 + c4 * 4);
        d[0] = __floats2half2_rn(t[c4 * 4 + 0][kk], t[c4 * 4 + 1][kk]);
        d[1] = __floats2half2_rn(t[c4 * 4 + 2][kk], t[c4 * 4 + 3][kk]);
    }
}

// ---------------------------------------------------------------------------
// Kernel 1a: fused QKV projection GEMMs, grid (32, 8, 3).
// C[m][n] = sum_k X[m][k] * Wt[n][k]; half output.
// ---------------------------------------------------------------------------
__device__ __forceinline__ void hgemm_body(
    const __half* __restrict__ A, const __half* __restrict__ Bm,
    void* __restrict__ Cout, const float* __restrict__ bias, int out_half,
    char* smc, int m0, int n0)
{
    __half* As = (__half*)smc;            // [2][128][G_LD]
    __half* Bs = As + 2 * G_BUF;

    const int tid = threadIdx.x;
    const int w = tid >> 5, lane = tid & 31;
    const int wm = w & 1, wn = w >> 1;

    auto prefetch = [&](int s, int buf) {
        const int k0 = s * 64;
        __half* Ab = As + buf * G_BUF;
        __half* Bb = Bs + buf * G_BUF;
#pragma unroll
        for (int i = 0; i < 4; i++) {
            int idx = tid + i * 256;
            int r = idx >> 3, c = idx & 7;
            cp16h(&Ab[r * G_LD + c * 8], A + (size_t)(m0 + r) * 1024 + k0 + c * 8);
            cp16h(&Bb[r * G_LD + c * 8], Bm + (size_t)(n0 + r) * 1024 + k0 + c * 8);
        }
        cp_commit();
    };

    HFragC acc[4][2];
#pragma unroll
    for (int i = 0; i < 4; i++) { wmma::fill_fragment(acc[i][0], 0.0f); wmma::fill_fragment(acc[i][1], 0.0f); }

    prefetch(0, 0);
    for (int s = 0; s < 16; s++) {
        const int buf = s & 1;
        if (s < 15) { prefetch(s + 1, buf ^ 1); cp_wait<1>(); } else { cp_wait<0>(); }
        __syncthreads();
        __half* Ab = As + buf * G_BUF;
        __half* Bb = Bs + buf * G_BUF;
#pragma unroll
        for (int ks = 0; ks < 4; ks++) {
            HFragA a[4]; HFragBc bb[2];
#pragma unroll
            for (int i = 0; i < 4; i++)
                wmma::load_matrix_sync(a[i], &Ab[(wm * 64 + i * 16) * G_LD + ks * 16], G_LD);
#pragma unroll
            for (int j = 0; j < 2; j++)
                wmma::load_matrix_sync(bb[j], &Bb[(wn * 32 + j * 16) * G_LD + ks * 16], G_LD);
#pragma unroll
            for (int i = 0; i < 4; i++)
#pragma unroll
                for (int j = 0; j < 2; j++) wmma::mma_sync(acc[i][j], a[i], bb[j], acc[i][j]);
        }
        __syncthreads();
    }

    float* stg = (float*)smc + w * 576;
    const int r = lane >> 1, cq = (lane & 1) * 16;
    float4 bv[4];
    if (!out_half) {
#pragma unroll
        for (int q = 0; q < 4; q++)
            bv[q] = bias ? *(const float4*)&bias[n0 + wn * 32 + cq + q * 4]
                         : make_float4(0.f, 0.f, 0.f, 0.f);
    }
#pragma unroll
    for (int i = 0; i < 4; i++) {
        wmma::store_matrix_sync(stg,      acc[i][0], 36, wmma::mem_row_major);
        wmma::store_matrix_sync(stg + 16, acc[i][1], 36, wmma::mem_row_major);
        __syncwarp();
        float4 v[4];
#pragma unroll
        for (int q = 0; q < 4; q++) v[q] = *(float4*)&stg[r * 36 + cq + q * 4];
        size_t gr = (size_t)(m0 + wm * 64 + i * 16 + r) * 1024 + n0 + wn * 32 + cq;
        if (out_half) {
            __half hb[16];
#pragma unroll
            for (int q = 0; q < 4; q++) {
                ((__half2*)hb)[2 * q + 0] = __floats2half2_rn(v[q].x, v[q].y);
                ((__half2*)hb)[2 * q + 1] = __floats2half2_rn(v[q].z, v[q].w);
            }
            __half* hC = (__half*)Cout;
            *(uint4*)&hC[gr]     = ((uint4*)hb)[0];
            *(uint4*)&hC[gr + 8] = ((uint4*)hb)[1];
        } else {
            float* fC = (float*)Cout;
#pragma unroll
            for (int q = 0; q < 4; q++) {
                v[q].x += bv[q].x; v[q].y += bv[q].y; v[q].z += bv[q].z; v[q].w += bv[q].w;
                *(float4*)&fC[gr + q * 4] = v[q];
            }
        }
        __syncwarp();
    }
}

__global__ void __launch_bounds__(256, 2)
qkvproj_kernel()
{
    extern __shared__ char smc[];
    const int which = blockIdx.z;
    const __half* A = (which == 0) ? g_hxq : (which == 1) ? g_hxk : g_hxv;
    const __half* Bm = (which == 0) ? g_hwq : (which == 1) ? g_hwk : g_hwv;
    __half* C = (which == 0) ? g_q : (which == 1) ? g_k : g_v;
    hgemm_body(A, Bm, C, nullptr, 1, smc, blockIdx.x * 128, blockIdx.y * 128);
}

__global__ void __launch_bounds__(256, 2)
outproj_kernel(const float* __restrict__ bias, float* __restrict__ out)
{
    extern __shared__ char smc[];
    hgemm_body(g_ctx, g_hwp, out, bias, 0, smc, blockIdx.x * 128, blockIdx.y * 128);
}

// ---------------------------------------------------------------------------
// Kernel 2: fused attention (fp16 operands, fp32 scores/softmax).
// Phase 3 reads fp32 probs from the strip (L2-hot) and converts in-kernel —
// no separate half-P global array.
// ---------------------------------------------------------------------------
__global__ void __launch_bounds__(256, 2)
attn_kernel(float* __restrict__ attn)
{
    extern __shared__ char smc[];
    __half* Qs = (__half*)smc;                     // [64][Q_LD]
    __half* Kv = (__half*)(smc + KV_OFF);          // [2][128][K_LD]
    __half* As3 = (__half*)(smc + KV_OFF);         // [64][P_LD]
    __half* Vs3 = (__half*)(smc + KV_OFF + QT * P_LD * 2);   // [128][K_LD]
    float* red  = (float*)(smc + KV_OFF);                    // [64][R_LD]
    float* red2 = (float*)(smc + KV_OFF + QT * P_LD * 2);    // [64][R_LD]

    const int bh = blockIdx.y;
    const int b = bh / H, h = bh % H;
    const int q0 = blockIdx.x * QT;
    const int tid = threadIdx.x;
    const int warp = tid >> 5, lane = tid & 31;

    float* strip = attn + ((size_t)(h * B + b) * S + q0) * S;    // [64][1024] f32

    // ---- phase 1: scores = QK^T/32 -> strip (f32) ----
    {
#pragma unroll
        for (int i = 0; i < 2; i++) {
            int idx = tid + i * 256;
            int r = idx >> 3, c = idx & 7;
            cp16h(&Qs[r * Q_LD + c * 8], g_q + ((size_t)(b * S + q0 + r)) * 1024 + h * 64 + c * 8);
        }
        auto prefetchK = [&](int c, int buf) {
            __half* Kb = Kv + buf * CK * K_LD;
#pragma unroll
            for (int i = 0; i < 4; i++) {
                int idx = tid + i * 256;
                int r = idx >> 3, cc = idx & 7;
                cp16h(&Kb[r * K_LD + cc * 8],
                      g_k + ((size_t)(b * S + c * CK + r)) * 1024 + h * 64 + cc * 8);
            }
            cp_commit();
        };
        prefetchK(0, 0);

        const int qh = warp >> 2;
        const int kw = warp & 3;

        for (int c = 0; c < S / CK; c++) {
            const int buf = c & 1;
            if (c < 7) { prefetchK(c + 1, buf ^ 1); cp_wait<1>(); } else { cp_wait<0>(); }
            __syncthreads();
            __half* Kb = Kv + buf * CK * K_LD;

            HFragC acc[2][2];
#pragma unroll
            for (int i = 0; i < 2; i++) { wmma::fill_fragment(acc[i][0], 0.0f); wmma::fill_fragment(acc[i][1], 0.0f); }
#pragma unroll
            for (int ks = 0; ks < 4; ks++) {
                HFragA a[2]; HFragBc bb[2];
#pragma unroll
                for (int i = 0; i < 2; i++)
                    wmma::load_matrix_sync(a[i], &Qs[(qh * 32 + i * 16) * Q_LD + ks * 16], Q_LD);
#pragma unroll
                for (int j = 0; j < 2; j++)
                    wmma::load_matrix_sync(bb[j], &Kb[(kw * 32 + j * 16) * K_LD + ks * 16], K_LD);
#pragma unroll
                for (int i = 0; i < 2; i++)
#pragma unroll
                    for (int j = 0; j < 2; j++) wmma::mma_sync(acc[i][j], a[i], bb[j], acc[i][j]);
            }
#pragma unroll
            for (int i = 0; i < 2; i++)
#pragma unroll
                for (int j = 0; j < 2; j++) {
#pragma unroll
                    for (int e = 0; e < acc[i][j].num_elements; e++) acc[i][j].x[e] *= INV_SCALE;
                    wmma::store_matrix_sync(strip + (size_t)(qh * 32 + i * 16) * S + c * CK + kw * 32 + j * 16,
                                            acc[i][j], S, wmma::mem_row_major);
                }
            __syncthreads();
        }
    }

    // ---- phase 2: softmax in place (f32) ----
#pragma unroll
    for (int rr = 0; rr < 8; rr++) {
        const int row = warp * 8 + rr;
        float* p = strip + (size_t)row * S;
        float4 v[8];
#pragma unroll
        for (int i = 0; i < 8; i++) v[i] = *(float4*)&p[i * 128 + lane * 4];
        float m = -1e30f;
#pragma unroll
        for (int i = 0; i < 8; i++)
            m = fmaxf(m, fmaxf(fmaxf(v[i].x, v[i].y), fmaxf(v[i].z, v[i].w)));
#pragma unroll
        for (int o = 16; o; o >>= 1) m = fmaxf(m, __shfl_xor_sync(0xffffffffu, m, o));
        float s = 0.0f;
#pragma unroll
        for (int i = 0; i < 8; i++) {
            v[i].x = __expf(v[i].x - m); v[i].y = __expf(v[i].y - m);
            v[i].z = __expf(v[i].z - m); v[i].w = __expf(v[i].w - m);
            s += (v[i].x + v[i].y) + (v[i].z + v[i].w);
        }
#pragma unroll
        for (int o = 16; o; o >>= 1) s += __shfl_xor_sync(0xffffffffu, s, o);
        const float inv = 1.0f / s;
#pragma unroll
        for (int i = 0; i < 8; i++) {
            float4 q; q.x = v[i].x * inv; q.y = v[i].y * inv; q.z = v[i].z * inv; q.w = v[i].w * inv;
            *(float4*)&p[i * 128 + lane * 4] = q;
        }
    }
    __syncthreads();

    // ---- phase 3: ctx = P V (P read back fp32 from strip, converted here) ----
    {
        const int kg = warp >> 2;
        const int qh = (warp >> 1) & 1;
        const int vn = warp & 1;

        HFragC pacc[2][2];
#pragma unroll
        for (int i = 0; i < 2; i++) { wmma::fill_fragment(pacc[i][0], 0.0f); wmma::fill_fragment(pacc[i][1], 0.0f); }

        for (int c = 0; c < S / CK; c++) {
            // V chunk via cp.async (overlaps with P conversion below)
#pragma unroll
            for (int i = 0; i < 4; i++) {
                int idx = tid + i * 256;
                int r = idx >> 3, cc = idx & 7;
                cp16h(&Vs3[r * K_LD + cc * 8],
                      g_v + ((size_t)(b * S + c * CK + r)) * 1024 + h * 64 + cc * 8);
            }
            cp_commit();
            // P chunk 64x128 f32 -> half smem (strip lines are L2-hot)
#pragma unroll
            for (int i = 0; i < 8; i++) {
                int lin = tid + i * 256;           // 2048 float4s
                int r = lin >> 5, c4 = lin & 31;
                float4 v = *(const float4*)&strip[(size_t)r * S + c * CK + c4 * 4];
                uint2 pk;
                ((__half2*)&pk)[0] = __floats2half2_rn(v.x, v.y);
                ((__half2*)&pk)[1] = __floats2half2_rn(v.z, v.w);
                *(uint2*)&As3[r * P_LD + c4 * 4] = pk;
            }
            cp_wait<0>();
            __syncthreads();
#pragma unroll
            for (int ks = 0; ks < 4; ks++) {
                const int kk = kg * 64 + ks * 16;
                HFragA a[2]; HFragBr bb[2];
#pragma unroll
                for (int i = 0; i < 2; i++)
                    wmma::load_matrix_sync(a[i], &As3[(qh * 32 + i * 16) * P_LD + kk], P_LD);
#pragma unroll
                for (int j = 0; j < 2; j++)
                    wmma::load_matrix_sync(bb[j], &Vs3[kk * K_LD + vn * 32 + j * 16], K_LD);
#pragma unroll
                for (int i = 0; i < 2; i++)
#pragma unroll
                    for (int j = 0; j < 2; j++) wmma::mma_sync(pacc[i][j], a[i], bb[j], pacc[i][j]);
            }
            __syncthreads();
        }

        if (kg == 1) {
#pragma unroll
            for (int i = 0; i < 2; i++)
#pragma unroll
                for (int j = 0; j < 2; j++)
                    wmma::store_matrix_sync(&red[(qh * 32 + i * 16) * R_LD + vn * 32 + j * 16],
                                            pacc[i][j], R_LD, wmma::mem_row_major);
        }
        __syncthreads();
        if (kg == 0) {
#pragma unroll
            for (int i = 0; i < 2; i++)
#pragma unroll
                for (int j = 0; j < 2; j++) {
                    HFragC other;
                    wmma::load_matrix_sync(other, &red[(qh * 32 + i * 16) * R_LD + vn * 32 + j * 16],
                                           R_LD, wmma::mem_row_major);
#pragma unroll
                    for (int e = 0; e < pacc[i][j].num_elements; e++) pacc[i][j].x[e] += other.x[e];
                    wmma::store_matrix_sync(&red2[(qh * 32 + i * 16) * R_LD + vn * 32 + j * 16],
                                            pacc[i][j], R_LD, wmma::mem_row_major);
                }
        }
        __syncthreads();
#pragma unroll
        for (int i = 0; i < 8; i++) {
            int lin = tid + i * 256;
            int r = lin >> 5, c2 = lin & 31;
            float2 t = *(float2*)&red2[r * R_LD + c2 * 2];
            __half2* dst = (__half2*)(g_ctx + ((size_t)(b * S + q0 + r)) * 1024 + h * 64 + c2 * 2);
            *dst = __floats2half2_rn(t.x, t.y);
        }
    }
}

// ---------------------------------------------------------------------------

extern "C" void kernel_launch(void* const* d_in, const int* in_sizes, int n_in,
                              void* d_out, int out_size)
{
    const float* query  = (const float*)d_in[0];
    const float* key    = (const float*)d_in[1];
    const float* value  = (const float*)d_in[2];
    const float* w_q    = (const float*)d_in[3];
    const float* w_k    = (const float*)d_in[4];
    const float* w_v    = (const float*)d_in[5];
    const float* w_proj = (const float*)d_in[6];
    const float* b_proj = (const float*)d_in[7];

    float* out  = (float*)d_out;            // [B, S, D]
    float* attn = out + OUT_ELEMS;          // [H*B, S, S]

    cudaFuncSetAttribute(qkvproj_kernel, cudaFuncAttributeMaxDynamicSharedMemorySize, (int)GEMM_SMEM);
    cudaFuncSetAttribute(outproj_kernel, cudaFuncAttributeMaxDynamicSharedMemorySize, (int)GEMM_SMEM);
    cudaFuncSetAttribute(attn_kernel, cudaFuncAttributeMaxDynamicSharedMemorySize, (int)ATTN_SMEM);

    __half* hwp;
    cudaGetSymbolAddress((void**)&hwp, g_hwp);

    const int nX4 = (int)((size_t)B * S * D / 4);   // 1,048,576
    const int nP4 = (int)((size_t)D * D / 4);       // 262,144
    f2h3_kernel<<<dim3((nX4 + 255) / 256, 3), 256>>>(
        (const float4*)query, (const float4*)key, (const float4*)value, nX4);
    f2h_kernel<<<(nP4 + 255) / 256, 256>>>((const float4*)w_proj, (__half2*)hwp, nP4);
    wtrans_kernel<<<dim3(16, 16, 3), 256>>>(w_q, w_k, w_v);

    qkvproj_kernel<<<dim3(32, 8, 3), 256, GEMM_SMEM>>>();
    attn_kernel<<<dim3(S / QT, HB), 256, ATTN_SMEM>>>(attn);
    outproj_kernel<<<dim3(32, 8), 256, GEMM_SMEM>>>(b_proj, out);
}

// round 14
// speedup vs baseline: 2.8711x; 1.0324x over previous
#include <cuda_runtime.h>
#include <cstdint>
#include <cuda_fp16.h>
#include <mma.h>

using namespace nvcuda;

namespace {
constexpr int B  = 4;
constexpr int H  = 16;
constexpr int S  = 1024;
constexpr int D  = 1024;
constexpr int HB = H * B;
constexpr float INV_SCALE = 1.0f / 32.0f;        // 1/sqrt(D)
constexpr size_t OUT_ELEMS = (size_t)B * S * D;

// half GEMM tiling (3-stage pipeline)
constexpr int G_LD = 72;                         // halfs per smem row (144B)
constexpr int G_BUF = 128 * G_LD;                // halfs per operand buffer
constexpr size_t GEMM_SMEM = (size_t)6 * G_BUF * 2;   // 3 bufs x 2 ops = 110592

// attention tiling
constexpr int QT = 64;
constexpr int CK = 128;
constexpr int Q_LD = 72;     // halfs
constexpr int K_LD = 72;     // halfs
constexpr int P_LD = 136;    // halfs
constexpr int R_LD = 68;     // floats
constexpr int KV_OFF = QT * Q_LD * 2;            // 9216 bytes
constexpr int KBUF_BYTES = CK * K_LD * 2;        // 18432
constexpr size_t ATTN_SMEM = (size_t)KV_OFF + 3 * KBUF_BYTES;   // 64512
}

// Scratch (__device__ globals; allocation-free rule)
__device__ __half g_hxq[(size_t)B * S * D];
__device__ __half g_hxk[(size_t)B * S * D];
__device__ __half g_hxv[(size_t)B * S * D];
__device__ __half g_hwq[(size_t)D * D];          // transposed [n][d]
__device__ __half g_hwk[(size_t)D * D];
__device__ __half g_hwv[(size_t)D * D];
__device__ __half g_hwp[(size_t)D * D];          // [n][k]
__device__ __half g_q[(size_t)B * S * D];        // proj outputs, [m][h*64+k]
__device__ __half g_k[(size_t)B * S * D];
__device__ __half g_v[(size_t)B * S * D];
__device__ __half g_ctx[(size_t)B * S * D];      // [m][h*64+v]

using HFragA  = wmma::fragment<wmma::matrix_a, 16, 16, 16, __half, wmma::row_major>;
using HFragBr = wmma::fragment<wmma::matrix_b, 16, 16, 16, __half, wmma::row_major>;
using HFragBc = wmma::fragment<wmma::matrix_b, 16, 16, 16, __half, wmma::col_major>;
using HFragC  = wmma::fragment<wmma::accumulator, 16, 16, 16, float>;

__device__ __forceinline__ void cp16h(__half* dst, const __half* src) {
    unsigned int s = (unsigned int)__cvta_generic_to_shared(dst);
    asm volatile("cp.async.cg.shared.global [%0], [%1], 16;" :: "r"(s), "l"(src));
}
__device__ __forceinline__ void cp_commit() { asm volatile("cp.async.commit_group;"); }
template <int N> __device__ __forceinline__ void cp_wait() {
    asm volatile("cp.async.wait_group %0;" :: "n"(N));
}

// ---------------------------------------------------------------------------
// Kernel 0a: fp32 -> fp16 for the three X tensors in one launch (y-indexed).
// ---------------------------------------------------------------------------
__global__ void __launch_bounds__(256)
f2h3_kernel(const float4* __restrict__ s0, const float4* __restrict__ s1,
            const float4* __restrict__ s2, int n4)
{
    const float4* src = (blockIdx.y == 0) ? s0 : (blockIdx.y == 1) ? s1 : s2;
    __half2* dst = (blockIdx.y == 0) ? (__half2*)g_hxq
                 : (blockIdx.y == 1) ? (__half2*)g_hxk : (__half2*)g_hxv;
    int i = blockIdx.x * 256 + threadIdx.x;
    if (i < n4) {
        float4 v = src[i];
        dst[2 * i + 0] = __floats2half2_rn(v.x, v.y);
        dst[2 * i + 1] = __floats2half2_rn(v.z, v.w);
    }
}

__global__ void __launch_bounds__(256)
f2h_kernel(const float4* __restrict__ src, __half2* __restrict__ dst, int n4)
{
    int i = blockIdx.x * 256 + threadIdx.x;
    if (i < n4) {
        float4 v = src[i];
        dst[2 * i + 0] = __floats2half2_rn(v.x, v.y);
        dst[2 * i + 1] = __floats2half2_rn(v.z, v.w);
    }
}

// ---------------------------------------------------------------------------
// Kernel 0b: W[h][d][kk] -> Wt[(h*64+kk)][d] in fp16. grid (16, 16, 3).
// ---------------------------------------------------------------------------
__global__ void __launch_bounds__(256)
wtrans_kernel(const float* __restrict__ wq, const float* __restrict__ wk,
              const float* __restrict__ wv)
{
    const int which = blockIdx.z;
    const float* W = (which == 0) ? wq : (which == 1) ? wk : wv;
    __half* OUT    = (which == 0) ? g_hwq : (which == 1) ? g_hwk : g_hwv;

    const int h  = blockIdx.y;
    const int d0 = blockIdx.x * 64;
    const int tid = threadIdx.x;
    __shared__ float t[64][65];

#pragma unroll
    for (int i = 0; i < 4; i++) {
        int idx = tid + i * 256;
        int r = idx >> 4, c4 = idx & 15;
        float4 v = *(const float4*)(W + ((size_t)h * 1024 + d0 + r) * 64 + c4 * 4);
        t[r][c4 * 4 + 0] = v.x; t[r][c4 * 4 + 1] = v.y;
        t[r][c4 * 4 + 2] = v.z; t[r][c4 * 4 + 3] = v.w;
    }
    __syncthreads();
#pragma unroll
    for (int i = 0; i < 4; i++) {
        int idx = tid + i * 256;
        int kk = idx >> 4, c4 = idx & 15;
        __half2* d = (__half2*)(OUT + ((size_t)h * 64 + kk) * 1024 + d0 + c4 * 4);
        d[0] = __floats2half2_rn(t[c4 * 4 + 0][kk], t[c4 * 4 + 1][kk]);
        d[1] = __floats2half2_rn(t[c4 * 4 + 2][kk], t[c4 * 4 + 3][kk]);
    }
}

// ---------------------------------------------------------------------------
// Shared GEMM body: 128x128 CTA tile, 8 warps (64x32 warp tile), K slabs of
// 64, 3-buffer cp.async pipeline with ONE __syncthreads per slab.
// ---------------------------------------------------------------------------
__device__ __forceinline__ void hgemm_body(
    const __half* __restrict__ A, const __half* __restrict__ Bm,
    void* __restrict__ Cout, const float* __restrict__ bias, int out_half,
    char* smc, int m0, int n0)
{
    __half* As = (__half*)smc;            // [3][128][G_LD]
    __half* Bs = As + 3 * G_BUF;          // [3][128][G_LD]

    const int tid = threadIdx.x;
    const int w = tid >> 5, lane = tid & 31;
    const int wm = w & 1, wn = w >> 1;

    auto prefetch = [&](int s, int buf) {
        const int k0 = s * 64;
        __half* Ab = As + buf * G_BUF;
        __half* Bb = Bs + buf * G_BUF;
#pragma unroll
        for (int i = 0; i < 4; i++) {
            int idx = tid + i * 256;
            int r = idx >> 3, c = idx & 7;
            cp16h(&Ab[r * G_LD + c * 8], A + (size_t)(m0 + r) * 1024 + k0 + c * 8);
            cp16h(&Bb[r * G_LD + c * 8], Bm + (size_t)(n0 + r) * 1024 + k0 + c * 8);
        }
        cp_commit();
    };

    HFragC acc[4][2];
#pragma unroll
    for (int i = 0; i < 4; i++) { wmma::fill_fragment(acc[i][0], 0.0f); wmma::fill_fragment(acc[i][1], 0.0f); }

    prefetch(0, 0);
    prefetch(1, 1);
    for (int s = 0; s < 16; s++) {
        const int buf = s % 3;
        if (s < 15) cp_wait<1>(); else cp_wait<0>();
        __syncthreads();
        if (s + 2 < 16) prefetch(s + 2, (s + 2) % 3);
        __half* Ab = As + buf * G_BUF;
        __half* Bb = Bs + buf * G_BUF;
#pragma unroll
        for (int ks = 0; ks < 4; ks++) {
            HFragA a[4]; HFragBc bb[2];
#pragma unroll
            for (int i = 0; i < 4; i++)
                wmma::load_matrix_sync(a[i], &Ab[(wm * 64 + i * 16) * G_LD + ks * 16], G_LD);
#pragma unroll
            for (int j = 0; j < 2; j++)
                wmma::load_matrix_sync(bb[j], &Bb[(wn * 32 + j * 16) * G_LD + ks * 16], G_LD);
#pragma unroll
            for (int i = 0; i < 4; i++)
#pragma unroll
                for (int j = 0; j < 2; j++) wmma::mma_sync(acc[i][j], a[i], bb[j], acc[i][j]);
        }
    }
    __syncthreads();      // epilogue staging aliases buffer 0

    float* stg = (float*)smc + w * 576;
    const int r = lane >> 1, cq = (lane & 1) * 16;
    float4 bv[4];
    if (!out_half) {
#pragma unroll
        for (int q = 0; q < 4; q++)
            bv[q] = bias ? *(const float4*)&bias[n0 + wn * 32 + cq + q * 4]
                         : make_float4(0.f, 0.f, 0.f, 0.f);
    }
#pragma unroll
    for (int i = 0; i < 4; i++) {
        wmma::store_matrix_sync(stg,      acc[i][0], 36, wmma::mem_row_major);
        wmma::store_matrix_sync(stg + 16, acc[i][1], 36, wmma::mem_row_major);
        __syncwarp();
        float4 v[4];
#pragma unroll
        for (int q = 0; q < 4; q++) v[q] = *(float4*)&stg[r * 36 + cq + q * 4];
        size_t gr = (size_t)(m0 + wm * 64 + i * 16 + r) * 1024 + n0 + wn * 32 + cq;
        if (out_half) {
            __half hb[16];
#pragma unroll
            for (int q = 0; q < 4; q++) {
                ((__half2*)hb)[2 * q + 0] = __floats2half2_rn(v[q].x, v[q].y);
                ((__half2*)hb)[2 * q + 1] = __floats2half2_rn(v[q].z, v[q].w);
            }
            __half* hC = (__half*)Cout;
            *(uint4*)&hC[gr]     = ((uint4*)hb)[0];
            *(uint4*)&hC[gr + 8] = ((uint4*)hb)[1];
        } else {
            float* fC = (float*)Cout;
#pragma unroll
            for (int q = 0; q < 4; q++) {
                v[q].x += bv[q].x; v[q].y += bv[q].y; v[q].z += bv[q].z; v[q].w += bv[q].w;
                *(float4*)&fC[gr + q * 4] = v[q];
            }
        }
        __syncwarp();
    }
}

__global__ void __launch_bounds__(256, 2)
qkvproj_kernel()
{
    extern __shared__ char smc[];
    const int which = blockIdx.z;
    const __half* A = (which == 0) ? g_hxq : (which == 1) ? g_hxk : g_hxv;
    const __half* Bm = (which == 0) ? g_hwq : (which == 1) ? g_hwk : g_hwv;
    __half* C = (which == 0) ? g_q : (which == 1) ? g_k : g_v;
    hgemm_body(A, Bm, C, nullptr, 1, smc, blockIdx.x * 128, blockIdx.y * 128);
}

__global__ void __launch_bounds__(256, 2)
outproj_kernel(const float* __restrict__ bias, float* __restrict__ out)
{
    extern __shared__ char smc[];
    hgemm_body(g_ctx, g_hwp, out, bias, 0, smc, blockIdx.x * 128, blockIdx.y * 128);
}

// ---------------------------------------------------------------------------
// Kernel 2: fused attention (fp16 operands, fp32 scores/softmax).
// Phase 1: 3-buffer K pipeline, one sync per chunk.
// ---------------------------------------------------------------------------
__global__ void __launch_bounds__(256, 2)
attn_kernel(float* __restrict__ attn)
{
    extern __shared__ char smc[];
    __half* Qs = (__half*)smc;                     // [64][Q_LD]
    __half* Kv = (__half*)(smc + KV_OFF);          // [3][128][K_LD]
    __half* As3 = (__half*)(smc + KV_OFF);         // [64][P_LD]
    __half* Vs3 = (__half*)(smc + KV_OFF + QT * P_LD * 2);   // [128][K_LD]
    float* red  = (float*)(smc + KV_OFF);                    // [64][R_LD]
    float* red2 = (float*)(smc + KV_OFF + QT * P_LD * 2);    // [64][R_LD]

    const int bh = blockIdx.y;
    const int b = bh / H, h = bh % H;
    const int q0 = blockIdx.x * QT;
    const int tid = threadIdx.x;
    const int warp = tid >> 5, lane = tid & 31;

    float* strip = attn + ((size_t)(h * B + b) * S + q0) * S;    // [64][1024] f32

    // ---- phase 1: scores = QK^T/32 -> strip (f32) ----
    {
#pragma unroll
        for (int i = 0; i < 2; i++) {
            int idx = tid + i * 256;
            int r = idx >> 3, c = idx & 7;
            cp16h(&Qs[r * Q_LD + c * 8], g_q + ((size_t)(b * S + q0 + r)) * 1024 + h * 64 + c * 8);
        }
        auto prefetchK = [&](int c, int buf) {
            __half* Kb = Kv + buf * CK * K_LD;
#pragma unroll
            for (int i = 0; i < 4; i++) {
                int idx = tid + i * 256;
                int r = idx >> 3, cc = idx & 7;
                cp16h(&Kb[r * K_LD + cc * 8],
                      g_k + ((size_t)(b * S + c * CK + r)) * 1024 + h * 64 + cc * 8);
            }
            cp_commit();
        };
        prefetchK(0, 0);     // group also carries the Q tile
        prefetchK(1, 1);

        const int qh = warp >> 2;
        const int kw = warp & 3;

        for (int c = 0; c < S / CK; c++) {
            const int buf = c % 3;
            if (c < 7) cp_wait<1>(); else cp_wait<0>();
            __syncthreads();
            if (c + 2 < 8) prefetchK(c + 2, (c + 2) % 3);
            __half* Kb = Kv + buf * CK * K_LD;

            HFragC acc[2][2];
#pragma unroll
            for (int i = 0; i < 2; i++) { wmma::fill_fragment(acc[i][0], 0.0f); wmma::fill_fragment(acc[i][1], 0.0f); }
#pragma unroll
            for (int ks = 0; ks < 4; ks++) {
                HFragA a[2]; HFragBc bb[2];
#pragma unroll
                for (int i = 0; i < 2; i++)
                    wmma::load_matrix_sync(a[i], &Qs[(qh * 32 + i * 16) * Q_LD + ks * 16], Q_LD);
#pragma unroll
                for (int j = 0; j < 2; j++)
                    wmma::load_matrix_sync(bb[j], &Kb[(kw * 32 + j * 16) * K_LD + ks * 16], K_LD);
#pragma unroll
                for (int i = 0; i < 2; i++)
#pragma unroll
                    for (int j = 0; j < 2; j++) wmma::mma_sync(acc[i][j], a[i], bb[j], acc[i][j]);
            }
#pragma unroll
            for (int i = 0; i < 2; i++)
#pragma unroll
                for (int j = 0; j < 2; j++) {
#pragma unroll
                    for (int e = 0; e < acc[i][j].num_elements; e++) acc[i][j].x[e] *= INV_SCALE;
                    wmma::store_matrix_sync(strip + (size_t)(qh * 32 + i * 16) * S + c * CK + kw * 32 + j * 16,
                                            acc[i][j], S, wmma::mem_row_major);
                }
        }
        __syncthreads();     // all score stores visible before softmax
    }

    // ---- phase 2: softmax in place (f32) ----
#pragma unroll
    for (int rr = 0; rr < 8; rr++) {
        const int row = warp * 8 + rr;
        float* p = strip + (size_t)row * S;
        float4 v[8];
#pragma unroll
        for (int i = 0; i < 8; i++) v[i] = *(float4*)&p[i * 128 + lane * 4];
        float m = -1e30f;
#pragma unroll
        for (int i = 0; i < 8; i++)
            m = fmaxf(m, fmaxf(fmaxf(v[i].x, v[i].y), fmaxf(v[i].z, v[i].w)));
#pragma unroll
        for (int o = 16; o; o >>= 1) m = fmaxf(m, __shfl_xor_sync(0xffffffffu, m, o));
        float s = 0.0f;
#pragma unroll
        for (int i = 0; i < 8; i++) {
            v[i].x = __expf(v[i].x - m); v[i].y = __expf(v[i].y - m);
            v[i].z = __expf(v[i].z - m); v[i].w = __expf(v[i].w - m);
            s += (v[i].x + v[i].y) + (v[i].z + v[i].w);
        }
#pragma unroll
        for (int o = 16; o; o >>= 1) s += __shfl_xor_sync(0xffffffffu, s, o);
        const float inv = 1.0f / s;
#pragma unroll
        for (int i = 0; i < 8; i++) {
            float4 q; q.x = v[i].x * inv; q.y = v[i].y * inv; q.z = v[i].z * inv; q.w = v[i].w * inv;
            *(float4*)&p[i * 128 + lane * 4] = q;
        }
    }
    __syncthreads();

    // ---- phase 3: ctx = P V (P read back fp32 from strip, converted here) ----
    {
        const int kg = warp >> 2;
        const int qh = (warp >> 1) & 1;
        const int vn = warp & 1;

        HFragC pacc[2][2];
#pragma unroll
        for (int i = 0; i < 2; i++) { wmma::fill_fragment(pacc[i][0], 0.0f); wmma::fill_fragment(pacc[i][1], 0.0f); }

        for (int c = 0; c < S / CK; c++) {
#pragma unroll
            for (int i = 0; i < 4; i++) {
                int idx = tid + i * 256;
                int r = idx >> 3, cc = idx & 7;
                cp16h(&Vs3[r * K_LD + cc * 8],
                      g_v + ((size_t)(b * S + c * CK + r)) * 1024 + h * 64 + cc * 8);
            }
            cp_commit();
#pragma unroll
            for (int i = 0; i < 8; i++) {
                int lin = tid + i * 256;
                int r = lin >> 5, c4 = lin & 31;
                float4 v = *(const float4*)&strip[(size_t)r * S + c * CK + c4 * 4];
                uint2 pk;
                ((__half2*)&pk)[0] = __floats2half2_rn(v.x, v.y);
                ((__half2*)&pk)[1] = __floats2half2_rn(v.z, v.w);
                *(uint2*)&As3[r * P_LD + c4 * 4] = pk;
            }
            cp_wait<0>();
            __syncthreads();
#pragma unroll
            for (int ks = 0; ks < 4; ks++) {
                const int kk = kg * 64 + ks * 16;
                HFragA a[2]; HFragBr bb[2];
#pragma unroll
                for (int i = 0; i < 2; i++)
                    wmma::load_matrix_sync(a[i], &As3[(qh * 32 + i * 16) * P_LD + kk], P_LD);
#pragma unroll
                for (int j = 0; j < 2; j++)
                    wmma::load_matrix_sync(bb[j], &Vs3[kk * K_LD + vn * 32 + j * 16], K_LD);
#pragma unroll
                for (int i = 0; i < 2; i++)
#pragma unroll
                    for (int j = 0; j < 2; j++) wmma::mma_sync(pacc[i][j], a[i], bb[j], pacc[i][j]);
            }
            __syncthreads();
        }

        if (kg == 1) {
#pragma unroll
            for (int i = 0; i < 2; i++)
#pragma unroll
                for (int j = 0; j < 2; j++)
                    wmma::store_matrix_sync(&red[(qh * 32 + i * 16) * R_LD + vn * 32 + j * 16],
                                            pacc[i][j], R_LD, wmma::mem_row_major);
        }
        __syncthreads();
        if (kg == 0) {
#pragma unroll
            for (int i = 0; i < 2; i++)
#pragma unroll
                for (int j = 0; j < 2; j++) {
                    HFragC other;
                    wmma::load_matrix_sync(other, &red[(qh * 32 + i * 16) * R_LD + vn * 32 + j * 16],
                                           R_LD, wmma::mem_row_major);
#pragma unroll
                    for (int e = 0; e < pacc[i][j].num_elements; e++) pacc[i][j].x[e] += other.x[e];
                    wmma::store_matrix_sync(&red2[(qh * 32 + i * 16) * R_LD + vn * 32 + j * 16],
                                            pacc[i][j], R_LD, wmma::mem_row_major);
                }
        }
        __syncthreads();
#pragma unroll
        for (int i = 0; i < 8; i++) {
            int lin = tid + i * 256;
            int r = lin >> 5, c2 = lin & 31;
            float2 t = *(float2*)&red2[r * R_LD + c2 * 2];
            __half2* dst = (__half2*)(g_ctx + ((size_t)(b * S + q0 + r)) * 1024 + h * 64 + c2 * 2);
            *dst = __floats2half2_rn(t.x, t.y);
        }
    }
}

// ---------------------------------------------------------------------------

extern "C" void kernel_launch(void* const* d_in, const int* in_sizes, int n_in,
                              void* d_out, int out_size)
{
    const float* query  = (const float*)d_in[0];
    const float* key    = (const float*)d_in[1];
    const float* value  = (const float*)d_in[2];
    const float* w_q    = (const float*)d_in[3];
    const float* w_k    = (const float*)d_in[4];
    const float* w_v    = (const float*)d_in[5];
    const float* w_proj = (const float*)d_in[6];
    const float* b_proj = (const float*)d_in[7];

    float* out  = (float*)d_out;            // [B, S, D]
    float* attn = out + OUT_ELEMS;          // [H*B, S, S]

    cudaFuncSetAttribute(qkvproj_kernel, cudaFuncAttributeMaxDynamicSharedMemorySize, (int)GEMM_SMEM);
    cudaFuncSetAttribute(outproj_kernel, cudaFuncAttributeMaxDynamicSharedMemorySize, (int)GEMM_SMEM);
    cudaFuncSetAttribute(attn_kernel, cudaFuncAttributeMaxDynamicSharedMemorySize, (int)ATTN_SMEM);

    __half* hwp;
    cudaGetSymbolAddress((void**)&hwp, g_hwp);

    const int nX4 = (int)((size_t)B * S * D / 4);   // 1,048,576
    const int nP4 = (int)((size_t)D * D / 4);       // 262,144
    f2h3_kernel<<<dim3((nX4 + 255) / 256, 3), 256>>>(
        (const float4*)query, (const float4*)key, (const float4*)value, nX4);
    f2h_kernel<<<(nP4 + 255) / 256, 256>>>((const float4*)w_proj, (__half2*)hwp, nP4);
    wtrans_kernel<<<dim3(16, 16, 3), 256>>>(w_q, w_k, w_v);

    qkvproj_kernel<<<dim3(32, 8, 3), 256, GEMM_SMEM>>>();
    attn_kernel<<<dim3(S / QT, HB), 256, ATTN_SMEM>>>(attn);
    outproj_kernel<<<dim3(32, 8), 256, GEMM_SMEM>>>(b_proj, out);
}